// round 9
// baseline (speedup 1.0000x reference)
#include <cuda_runtime.h>
#include <cuda_bf16.h>

// SSIM loss — band kernel, p/m reformulation + packed f32x2 arithmetic.
// R7 structure (GROWS=8, stride-8 runs -> conflict-free XOR swizzle,
// 256 blocks). P-stream and M-stream processed as one f32x2 lane pair via
// inline PTX (add/mul/fma.rn.f32x2): halves FMA-pipe ops in both phases.

#define IMG    512
#define CROP   492
#define SHAVE  10
#define PLANE  (IMG * IMG)

#define NBANDS 16
#define RROWS  32
#define GROWS  8
#define NBATCH (RROWS / GROWS)   // 4
#define WID4   512
#define NT     512
#define NBLOCKS (NBANDS * 16)    // 256

#define SWZ4(i) ((i) ^ (((i) >> 3) & 7))
#define Q4(g, i) ((g) * WID4 + SWZ4(i))

#define SMEM_BYTES (GROWS * WID4 * 16)   // 65536

typedef unsigned long long u64;

#define PACK2(d, lo, hi)  asm("mov.b64 %0, {%1, %2};" : "=l"(d) : "f"(lo), "f"(hi))
#define UNPK2(lo, hi, s)  asm("mov.b64 {%0, %1}, %2;" : "=f"(lo), "=f"(hi) : "l"(s))
#define ADD2(d, a, b)     asm("add.rn.f32x2 %0, %1, %2;" : "=l"(d) : "l"(a), "l"(b))
#define MUL2(d, a, b)     asm("mul.rn.f32x2 %0, %1, %2;" : "=l"(d) : "l"(a), "l"(b))
#define FMA2(d, a, b, c)  asm("fma.rn.f32x2 %0, %1, %2, %3;" : "=l"(d) : "l"(a), "l"(b), "l"(c))

#define NEG1_BITS 0xBF800000BF800000ULL   // (-1.0f, -1.0f)

__device__ double   g_part[NBLOCKS];
__device__ unsigned g_count = 0;

__device__ __forceinline__ float yval(float c0, float c1, float c2)
{
    const float w0 = 65.738f  / 256.0f;
    const float w1 = 129.057f / 256.0f;
    const float w2 = 25.064f  / 256.0f;
    const float inv255 = 1.0f / 255.0f;
    return w0 * __saturatef(c0 * inv255)
         + w1 * __saturatef(c1 * inv255)
         + w2 * __saturatef(c2 * inv255);
}

// insert packed (p|m) into 11-deep window; maintain packed running sums
__device__ __forceinline__ void push2(
    u64 pm, u64 (&w)[11], u64& Spm, u64& Sqq, u64 NEG1)
{
    u64 old = w[0];
    ADD2(Spm, Spm, pm);
    FMA2(Spm, old, NEG1, Spm);        // Spm += pm - old
    FMA2(Sqq, pm, pm, Sqq);           // Sqq += pm^2
    u64 osq;
    MUL2(osq, old, old);
    FMA2(Sqq, osq, NEG1, Sqq);        // Sqq -= old^2
    #pragma unroll
    for (int k = 0; k < 10; k++) w[k] = w[k + 1];
    w[10] = pm;
}

__global__ __launch_bounds__(NT, 2)
void ssim_band_kernel(const float* __restrict__ sr, const float* __restrict__ hr,
                      float* __restrict__ out, const void* __restrict__ bs_ptr)
{
    extern __shared__ char smem_raw[];
    ulonglong2* cs = (ulonglong2*)smem_raw;    // [GROWS][WID4]: (Sp|Sm, Spp|Smm)

    __shared__ float  redf[NT / 32];
    __shared__ double redd[NT / 32];
    __shared__ int    s_last;

    const int t    = threadIdx.x;
    const int band = blockIdx.x;
    const int n    = blockIdx.y;
    const int oy0  = band * RROWS;

    const float* A = sr + (size_t)n * 3 * PLANE;
    const float* B = hr + (size_t)n * 3 * PLANE;

    const u64 NEG1 = NEG1_BITS;

    // zero cs plane once: halo cells stay zero forever
    for (int i = t; i < GROWS * WID4; i += NT)
        cs[i] = make_ulonglong2(0ULL, 0ULL);

    u64 w[11];
    #pragma unroll
    for (int k = 0; k < 11; k++) w[k] = 0ULL;
    u64 Spm = 0ULL, Sqq = 0ULL;

    const bool col_ok = (t < CROP);
    int ry  = oy0 - 5;
    int off = (ry + SHAVE) * IMG + (t + SHAVE);

    // ---- warm-up: 10 row inserts ----
    #pragma unroll
    for (int i = 0; i < 10; i++) {
        bool v = col_ok && (ry >= 0) && (ry < CROP);
        u64 pm = 0ULL;
        if (v) {
            float a = yval(A[off], A[off + PLANE], A[off + 2*PLANE]);
            float b = yval(B[off], B[off + PLANE], B[off + 2*PLANE]);
            PACK2(pm, a + b, a - b);
        }
        push2(pm, w, Spm, Sqq, NEG1);
        ry++; off += IMG;
    }
    __syncthreads();

    const float inv121 = 1.0f / 121.0f;
    const float C1 = 6.5025f;
    const float C2 = 58.5225f;

    float acc = 0.0f;

    #pragma unroll
    for (int jb = 0; jb < NBATCH; jb++) {
        // ---- vertical: insert GROWS rows, emit one 16B packed store ----
        #pragma unroll
        for (int g = 0; g < GROWS; g++) {
            int gy = oy0 + jb * GROWS + g;
            bool v = col_ok && (ry < CROP);
            u64 pm = 0ULL;
            if (v) {
                float a = yval(A[off], A[off + PLANE], A[off + 2*PLANE]);
                float b = yval(B[off], B[off + PLANE], B[off + 2*PLANE]);
                PACK2(pm, a + b, a - b);
            }
            push2(pm, w, Spm, Sqq, NEG1);
            ry++; off += IMG;
            if (col_ok && gy < CROP)
                cs[Q4(g, t + 5)] = make_ulonglong2(Spm, Sqq);
        }
        __syncthreads();

        // ---- horizontal: runs of 8 outputs, packed sliding windows ----
        if (t < 496) {
            int row = t / 62;             // 0..7
            int run = t % 62;             // 0..61
            int x0  = run * 8;
            int gy  = oy0 + jb * GROWS + row;
            if (gy < CROP) {
                u64 H1 = 0ULL, H2 = 0ULL;
                #pragma unroll
                for (int d = 0; d < 11; d++) {
                    ulonglong2 q = cs[Q4(row, x0 + d)];
                    ADD2(H1, H1, q.x);
                    ADD2(H2, H2, q.y);
                }
                #pragma unroll
                for (int mm = 0; mm < 8; mm++) {
                    if (x0 + mm < CROP) {
                        float HP, HM, HPP, HMM;
                        UNPK2(HP, HM, H1);
                        UNPK2(HPP, HMM, H2);
                        float muP = HP * inv121;
                        float muM = HM * inv121;
                        float muP2 = muP * muP;
                        float muM2 = muM * muM;
                        float mu1mu2 = 0.25f * (muP2 - muM2);
                        float musq   = 0.5f  * (muP2 + muM2);
                        float sab    = 0.25f * (HPP - HMM);
                        float ssq    = 0.5f  * (HPP + HMM);
                        float sigma12 = fmaf(sab, inv121, -mu1mu2);
                        float sigsum  = fmaf(ssq, inv121, -musq);
                        float num = fmaf(2.0f, mu1mu2, C1) * fmaf(2.0f, sigma12, C2);
                        float den = (musq + C1) * (sigsum + C2);
                        acc += 1.0f - __fdividef(num, den);
                    }
                    if (mm < 7) {
                        ulonglong2 qo = cs[Q4(row, x0 + mm)];
                        ulonglong2 qn = cs[Q4(row, x0 + mm + 11)];
                        ADD2(H1, H1, qn.x);
                        FMA2(H1, qo.x, NEG1, H1);
                        ADD2(H2, H2, qn.y);
                        FMA2(H2, qo.y, NEG1, H2);
                    }
                }
            }
        }
        __syncthreads();
    }

    // ---- block reduction -> per-block partial ----
    #pragma unroll
    for (int o = 16; o > 0; o >>= 1)
        acc += __shfl_down_sync(0xffffffffu, acc, o);
    int lane = t & 31, warp = t >> 5;
    if (lane == 0) redf[warp] = acc;
    __syncthreads();
    if (warp == 0) {
        float v = (lane < NT / 32) ? redf[lane] : 0.0f;
        #pragma unroll
        for (int o = 16; o > 0; o >>= 1)
            v += __shfl_down_sync(0xffffffffu, v, o);
        if (lane == 0)
            g_part[n * NBANDS + band] = (double)v;
    }

    // ---- last block performs the global reduction ----
    if (t == 0) {
        __threadfence();
        unsigned old = atomicAdd(&g_count, 1u);
        s_last = (old == NBLOCKS - 1) ? 1 : 0;
    }
    __syncthreads();
    if (s_last) {
        double v = (t < NBLOCKS) ? g_part[t] : 0.0;
        #pragma unroll
        for (int o = 16; o > 0; o >>= 1)
            v += __shfl_down_sync(0xffffffffu, v, o);
        if (lane == 0) redd[warp] = v;
        __syncthreads();
        if (warp == 0) {
            double s = (lane < NT / 32) ? redd[lane] : 0.0;
            #pragma unroll
            for (int o = 16; o > 0; o >>= 1)
                s += __shfl_down_sync(0xffffffffu, s, o);
            if (lane == 0) {
                float divisor = 16.0f;
                if (bs_ptr) {
                    int vi = *(const int*)bs_ptr;
                    if (vi > 0 && vi < 100000000) divisor = (float)vi;
                    else {
                        float vf = *(const float*)bs_ptr;
                        if (vf > 0.0f && vf < 1.0e8f) divisor = vf;
                    }
                }
                out[0]  = (float)(s / (double)divisor);
                g_count = 0;   // reset for next graph replay
            }
        }
    }
}

extern "C" void kernel_launch(void* const* d_in, const int* in_sizes, int n_in,
                              void* d_out, int out_size)
{
    const float* sr = (const float*)d_in[0];
    const float* hr = (const float*)d_in[1];
    const void* bs  = (n_in >= 3) ? d_in[2] : nullptr;
    float* out = (float*)d_out;

    cudaFuncSetAttribute(ssim_band_kernel,
                         cudaFuncAttributeMaxDynamicSharedMemorySize, SMEM_BYTES);

    dim3 grid(NBANDS, 16);
    ssim_band_kernel<<<grid, NT, SMEM_BYTES>>>(sr, hr, out, bs);
}

// round 10
// speedup vs baseline: 1.3462x; 1.3462x over previous
#include <cuda_runtime.h>
#include <cuda_bf16.h>

// SSIM loss — band kernel, p/m 4-quantity reformulation (R7 math), balanced
// 288-block grid. GROWS=7 rows/batch but horizontal runs keep STRIDE 8 so
// the XOR swizzle stays conflict-free (R8's stride-7 bug fixed): 62 runs x
// 7 rows = 434 active threads, 8 outputs each.

#define IMG    512
#define CROP   492
#define SHAVE  10
#define PLANE  (IMG * IMG)

#define NBANDS 18
#define RROWS  28
#define GROWS  7
#define NBATCH (RROWS / GROWS)   // 4
#define WID4   512
#define NT     512
#define NBLOCKS (NBANDS * 16)    // 288

#define SWZ4(i) ((i) ^ (((i) >> 3) & 7))
#define Q4(g, i) ((g) * WID4 + SWZ4(i))

#define SMEM_BYTES (GROWS * WID4 * 16)   // 57344

__device__ double   g_part[NBLOCKS];
__device__ unsigned g_count = 0;

__device__ __forceinline__ float yval(float c0, float c1, float c2)
{
    const float w0 = 65.738f  / 256.0f;
    const float w1 = 129.057f / 256.0f;
    const float w2 = 25.064f  / 256.0f;
    const float inv255 = 1.0f / 255.0f;
    return w0 * __saturatef(c0 * inv255)
         + w1 * __saturatef(c1 * inv255)
         + w2 * __saturatef(c2 * inv255);
}

__device__ __forceinline__ void push(
    float p, float m, float (&wp)[11], float (&wm)[11],
    float& Sp, float& Sm, float& Spp, float& Smm)
{
    float op = wp[0], om = wm[0];
    Sp  += p - op;
    Sm  += m - om;
    Spp += p * p - op * op;
    Smm += m * m - om * om;
    #pragma unroll
    for (int k = 0; k < 10; k++) { wp[k] = wp[k + 1]; wm[k] = wm[k + 1]; }
    wp[10] = p; wm[10] = m;
}

__global__ __launch_bounds__(NT, 2)
void ssim_band_kernel(const float* __restrict__ sr, const float* __restrict__ hr,
                      float* __restrict__ out, const void* __restrict__ bs_ptr)
{
    extern __shared__ char smem_raw[];
    float4* cs4 = (float4*)smem_raw;      // [GROWS][WID4] packed (Sp,Sm,Spp,Smm)

    __shared__ float  redf[NT / 32];
    __shared__ double redd[NT / 32];
    __shared__ int    s_last;

    const int t    = threadIdx.x;
    const int band = blockIdx.x;
    const int n    = blockIdx.y;
    const int oy0  = band * RROWS;

    const float* A = sr + (size_t)n * 3 * PLANE;
    const float* B = hr + (size_t)n * 3 * PLANE;

    // zero cs plane once: halo cells stay zero forever
    for (int i = t; i < GROWS * WID4; i += NT)
        cs4[i] = make_float4(0.f, 0.f, 0.f, 0.f);

    float wp[11], wm[11];
    #pragma unroll
    for (int k = 0; k < 11; k++) { wp[k] = 0.0f; wm[k] = 0.0f; }
    float Sp = 0.f, Sm = 0.f, Spp = 0.f, Smm = 0.f;

    const bool col_ok = (t < CROP);
    int ry  = oy0 - 5;
    int off = (ry + SHAVE) * IMG + (t + SHAVE);

    // ---- warm-up: 10 row inserts ----
    #pragma unroll
    for (int i = 0; i < 10; i++) {
        bool v = col_ok && (ry >= 0) && (ry < CROP);
        float p = 0.f, m = 0.f;
        if (v) {
            float a = yval(A[off], A[off + PLANE], A[off + 2*PLANE]);
            float b = yval(B[off], B[off + PLANE], B[off + 2*PLANE]);
            p = a + b; m = a - b;
        }
        push(p, m, wp, wm, Sp, Sm, Spp, Smm);
        ry++; off += IMG;
    }
    __syncthreads();

    const float inv121 = 1.0f / 121.0f;
    const float C1 = 6.5025f;
    const float C2 = 58.5225f;

    float acc = 0.0f;

    #pragma unroll
    for (int jb = 0; jb < NBATCH; jb++) {
        // ---- vertical: insert GROWS rows, emit one packed float4 each ----
        #pragma unroll
        for (int g = 0; g < GROWS; g++) {
            int gy = oy0 + jb * GROWS + g;
            bool v = col_ok && (ry < CROP);
            float p = 0.f, m = 0.f;
            if (v) {
                float a = yval(A[off], A[off + PLANE], A[off + 2*PLANE]);
                float b = yval(B[off], B[off + PLANE], B[off + 2*PLANE]);
                p = a + b; m = a - b;
            }
            push(p, m, wp, wm, Sp, Sm, Spp, Smm);
            ry++; off += IMG;
            if (col_ok && gy < CROP)
                cs4[Q4(g, t + 5)] = make_float4(Sp, Sm, Spp, Smm);
        }
        __syncthreads();

        // ---- horizontal: 62 runs x 7 rows, runs of 8 (stride-8 keeps
        //      the XOR swizzle conflict-free) ----
        if (t < 434) {
            int row = t / 62;             // 0..6
            int run = t % 62;             // 0..61
            int x0  = run * 8;            // 0..488
            int gy  = oy0 + jb * GROWS + row;
            if (gy < CROP) {
                float HP = 0.f, HM = 0.f, HPP = 0.f, HMM = 0.f;
                #pragma unroll
                for (int d = 0; d < 11; d++) {
                    float4 q = cs4[Q4(row, x0 + d)];
                    HP += q.x; HM += q.y; HPP += q.z; HMM += q.w;
                }
                #pragma unroll
                for (int mm = 0; mm < 8; mm++) {
                    if (x0 + mm < CROP) {
                        float muP = HP * inv121;
                        float muM = HM * inv121;
                        float muP2 = muP * muP;
                        float muM2 = muM * muM;
                        float mu1mu2 = 0.25f * (muP2 - muM2);
                        float musq   = 0.5f  * (muP2 + muM2);
                        float sab    = 0.25f * (HPP - HMM);   // box(ab)
                        float ssq    = 0.5f  * (HPP + HMM);   // box(a^2+b^2)
                        float sigma12 = fmaf(sab, inv121, -mu1mu2);
                        float sigsum  = fmaf(ssq, inv121, -musq);
                        float num = fmaf(2.0f, mu1mu2, C1) * fmaf(2.0f, sigma12, C2);
                        float den = (musq + C1) * (sigsum + C2);
                        acc += 1.0f - __fdividef(num, den);
                    }
                    if (mm < 7) {
                        float4 qo = cs4[Q4(row, x0 + mm)];
                        float4 qn = cs4[Q4(row, x0 + mm + 11)];
                        HP  += qn.x - qo.x;
                        HM  += qn.y - qo.y;
                        HPP += qn.z - qo.z;
                        HMM += qn.w - qo.w;
                    }
                }
            }
        }
        __syncthreads();
    }

    // ---- block reduction -> per-block partial ----
    #pragma unroll
    for (int o = 16; o > 0; o >>= 1)
        acc += __shfl_down_sync(0xffffffffu, acc, o);
    int lane = t & 31, warp = t >> 5;
    if (lane == 0) redf[warp] = acc;
    __syncthreads();
    if (warp == 0) {
        float v = (lane < NT / 32) ? redf[lane] : 0.0f;
        #pragma unroll
        for (int o = 16; o > 0; o >>= 1)
            v += __shfl_down_sync(0xffffffffu, v, o);
        if (lane == 0)
            g_part[n * NBANDS + band] = (double)v;
    }

    // ---- last block performs the global reduction ----
    if (t == 0) {
        __threadfence();
        unsigned old = atomicAdd(&g_count, 1u);
        s_last = (old == NBLOCKS - 1) ? 1 : 0;
    }
    __syncthreads();
    if (s_last) {
        double v = (t < NBLOCKS) ? g_part[t] : 0.0;
        #pragma unroll
        for (int o = 16; o > 0; o >>= 1)
            v += __shfl_down_sync(0xffffffffu, v, o);
        if (lane == 0) redd[warp] = v;
        __syncthreads();
        if (warp == 0) {
            double s = (lane < NT / 32) ? redd[lane] : 0.0;
            #pragma unroll
            for (int o = 16; o > 0; o >>= 1)
                s += __shfl_down_sync(0xffffffffu, s, o);
            if (lane == 0) {
                float divisor = 16.0f;
                if (bs_ptr) {
                    int vi = *(const int*)bs_ptr;
                    if (vi > 0 && vi < 100000000) divisor = (float)vi;
                    else {
                        float vf = *(const float*)bs_ptr;
                        if (vf > 0.0f && vf < 1.0e8f) divisor = vf;
                    }
                }
                out[0]  = (float)(s / (double)divisor);
                g_count = 0;   // reset for next graph replay
            }
        }
    }
}

extern "C" void kernel_launch(void* const* d_in, const int* in_sizes, int n_in,
                              void* d_out, int out_size)
{
    const float* sr = (const float*)d_in[0];
    const float* hr = (const float*)d_in[1];
    const void* bs  = (n_in >= 3) ? d_in[2] : nullptr;
    float* out = (float*)d_out;

    cudaFuncSetAttribute(ssim_band_kernel,
                         cudaFuncAttributeMaxDynamicSharedMemorySize, SMEM_BYTES);

    dim3 grid(NBANDS, 16);
    ssim_band_kernel<<<grid, NT, SMEM_BYTES>>>(sr, hr, out, bs);
}

// round 11
// speedup vs baseline: 1.4600x; 1.0846x over previous
#include <cuda_runtime.h>
#include <cuda_bf16.h>

// SSIM loss — half-band kernel: 256-thread blocks over 246 output columns,
// 4 blocks/SM for fine-grained barrier interleaving. p/m 4-quantity math,
// float4 smem plane, XOR swizzle, stride-8 horizontal runs.

#define IMG    512
#define CROP   492
#define SHAVE  10
#define PLANE  (IMG * IMG)

#define NBANDS 18
#define RROWS  28
#define GROWS  7
#define NBATCH (RROWS / GROWS)   // 4
#define HALF   246               // output columns per block
#define WID4   272               // smem row capacity (needs >= 258)
#define NT     256
#define NBLOCKS (NBANDS * 2 * 16)   // 576

#define SWZ4(i) ((i) ^ (((i) >> 3) & 7))
#define Q4(g, i) ((g) * WID4 + SWZ4(i))

#define SMEM_BYTES (GROWS * WID4 * 16)   // 30464

__device__ double   g_part[NBLOCKS];
__device__ unsigned g_count = 0;

__device__ __forceinline__ float yval(float c0, float c1, float c2)
{
    const float w0 = 65.738f  / 256.0f;
    const float w1 = 129.057f / 256.0f;
    const float w2 = 25.064f  / 256.0f;
    const float inv255 = 1.0f / 255.0f;
    return w0 * __saturatef(c0 * inv255)
         + w1 * __saturatef(c1 * inv255)
         + w2 * __saturatef(c2 * inv255);
}

__device__ __forceinline__ void push(
    float p, float m, float (&wp)[11], float (&wm)[11],
    float& Sp, float& Sm, float& Spp, float& Smm)
{
    float op = wp[0], om = wm[0];
    Sp  += p - op;
    Sm  += m - om;
    Spp += p * p - op * op;
    Smm += m * m - om * om;
    #pragma unroll
    for (int k = 0; k < 10; k++) { wp[k] = wp[k + 1]; wm[k] = wm[k + 1]; }
    wp[10] = p; wm[10] = m;
}

__global__ __launch_bounds__(NT, 4)
void ssim_band_kernel(const float* __restrict__ sr, const float* __restrict__ hr,
                      float* __restrict__ out, const void* __restrict__ bs_ptr)
{
    extern __shared__ char smem_raw[];
    float4* cs4 = (float4*)smem_raw;      // [GROWS][WID4] packed (Sp,Sm,Spp,Smm)

    __shared__ float  redf[NT / 32];
    __shared__ double redd[NT / 32];
    __shared__ int    s_last;

    const int t    = threadIdx.x;
    const int bx   = blockIdx.x;          // 0..35
    const int band = bx >> 1;             // 0..17
    const int half = bx & 1;              // 0..1
    const int n    = blockIdx.y;
    const int oy0  = band * RROWS;
    const int base = half * HALF;         // global x of local output 0

    const float* A = sr + (size_t)n * 3 * PLANE;
    const float* B = hr + (size_t)n * 3 * PLANE;

    // zero cs plane once: halo/pad cells stay zero forever
    for (int i = t; i < GROWS * WID4; i += NT)
        cs4[i] = make_float4(0.f, 0.f, 0.f, 0.f);

    float wp[11], wm[11];
    #pragma unroll
    for (int k = 0; k < 11; k++) { wp[k] = 0.0f; wm[k] = 0.0f; }
    float Sp = 0.f, Sm = 0.f, Spp = 0.f, Smm = 0.f;

    const int  gx     = base + t - 5;               // global Y-image column
    const bool col_ok = (gx >= 0) && (gx < CROP);
    int ry  = oy0 - 5;
    int off = (ry + SHAVE) * IMG + (gx + SHAVE);

    // ---- warm-up: 10 row inserts ----
    #pragma unroll
    for (int i = 0; i < 10; i++) {
        bool v = col_ok && (ry >= 0) && (ry < CROP);
        float p = 0.f, m = 0.f;
        if (v) {
            float a = yval(A[off], A[off + PLANE], A[off + 2*PLANE]);
            float b = yval(B[off], B[off + PLANE], B[off + 2*PLANE]);
            p = a + b; m = a - b;
        }
        push(p, m, wp, wm, Sp, Sm, Spp, Smm);
        ry++; off += IMG;
    }
    __syncthreads();

    const float inv121 = 1.0f / 121.0f;
    const float C1 = 6.5025f;
    const float C2 = 58.5225f;

    float acc = 0.0f;

    #pragma unroll
    for (int jb = 0; jb < NBATCH; jb++) {
        // ---- vertical: insert GROWS rows, emit packed float4 (zeros for
        //      invalid columns keep the halo correct) ----
        #pragma unroll
        for (int g = 0; g < GROWS; g++) {
            bool v = col_ok && (ry < CROP);
            float p = 0.f, m = 0.f;
            if (v) {
                float a = yval(A[off], A[off + PLANE], A[off + 2*PLANE]);
                float b = yval(B[off], B[off + PLANE], B[off + 2*PLANE]);
                p = a + b; m = a - b;
            }
            push(p, m, wp, wm, Sp, Sm, Spp, Smm);
            ry++; off += IMG;
            cs4[Q4(g, t)] = make_float4(Sp, Sm, Spp, Smm);
        }
        __syncthreads();

        // ---- horizontal: 31 runs x 7 rows, runs of 8 (stride-8 swizzle) ----
        if (t < 217) {
            int row = t / 31;             // 0..6
            int run = t % 31;             // 0..30
            int x0  = run * 8;            // 0..240
            int gy  = oy0 + jb * GROWS + row;
            if (gy < CROP) {
                float HP = 0.f, HM = 0.f, HPP = 0.f, HMM = 0.f;
                #pragma unroll
                for (int d = 0; d < 11; d++) {
                    float4 q = cs4[Q4(row, x0 + d)];
                    HP += q.x; HM += q.y; HPP += q.z; HMM += q.w;
                }
                #pragma unroll
                for (int mm = 0; mm < 8; mm++) {
                    if (x0 + mm < HALF) {
                        float muP = HP * inv121;
                        float muM = HM * inv121;
                        float muP2 = muP * muP;
                        float muM2 = muM * muM;
                        float mu1mu2 = 0.25f * (muP2 - muM2);
                        float musq   = 0.5f  * (muP2 + muM2);
                        float sab    = 0.25f * (HPP - HMM);
                        float ssq    = 0.5f  * (HPP + HMM);
                        float sigma12 = fmaf(sab, inv121, -mu1mu2);
                        float sigsum  = fmaf(ssq, inv121, -musq);
                        float num = fmaf(2.0f, mu1mu2, C1) * fmaf(2.0f, sigma12, C2);
                        float den = (musq + C1) * (sigsum + C2);
                        acc += 1.0f - __fdividef(num, den);
                    }
                    if (mm < 7) {
                        float4 qo = cs4[Q4(row, x0 + mm)];
                        float4 qn = cs4[Q4(row, x0 + mm + 11)];
                        HP  += qn.x - qo.x;
                        HM  += qn.y - qo.y;
                        HPP += qn.z - qo.z;
                        HMM += qn.w - qo.w;
                    }
                }
            }
        }
        __syncthreads();
    }

    // ---- block reduction -> per-block partial ----
    #pragma unroll
    for (int o = 16; o > 0; o >>= 1)
        acc += __shfl_down_sync(0xffffffffu, acc, o);
    int lane = t & 31, warp = t >> 5;
    if (lane == 0) redf[warp] = acc;
    __syncthreads();
    if (warp == 0) {
        float v = (lane < NT / 32) ? redf[lane] : 0.0f;
        #pragma unroll
        for (int o = 16; o > 0; o >>= 1)
            v += __shfl_down_sync(0xffffffffu, v, o);
        if (lane == 0)
            g_part[(n * NBANDS + band) * 2 + half] = (double)v;
    }

    // ---- last block performs the global reduction ----
    if (t == 0) {
        __threadfence();
        unsigned old = atomicAdd(&g_count, 1u);
        s_last = (old == NBLOCKS - 1) ? 1 : 0;
    }
    __syncthreads();
    if (s_last) {
        double v = 0.0;
        for (int i = t; i < NBLOCKS; i += NT) v += g_part[i];
        #pragma unroll
        for (int o = 16; o > 0; o >>= 1)
            v += __shfl_down_sync(0xffffffffu, v, o);
        if (lane == 0) redd[warp] = v;
        __syncthreads();
        if (warp == 0) {
            double s = (lane < NT / 32) ? redd[lane] : 0.0;
            #pragma unroll
            for (int o = 16; o > 0; o >>= 1)
                s += __shfl_down_sync(0xffffffffu, s, o);
            if (lane == 0) {
                float divisor = 16.0f;
                if (bs_ptr) {
                    int vi = *(const int*)bs_ptr;
                    if (vi > 0 && vi < 100000000) divisor = (float)vi;
                    else {
                        float vf = *(const float*)bs_ptr;
                        if (vf > 0.0f && vf < 1.0e8f) divisor = vf;
                    }
                }
                out[0]  = (float)(s / (double)divisor);
                g_count = 0;   // reset for next graph replay
            }
        }
    }
}

extern "C" void kernel_launch(void* const* d_in, const int* in_sizes, int n_in,
                              void* d_out, int out_size)
{
    const float* sr = (const float*)d_in[0];
    const float* hr = (const float*)d_in[1];
    const void* bs  = (n_in >= 3) ? d_in[2] : nullptr;
    float* out = (float*)d_out;

    cudaFuncSetAttribute(ssim_band_kernel,
                         cudaFuncAttributeMaxDynamicSharedMemorySize, SMEM_BYTES);

    dim3 grid(NBANDS * 2, 16);
    ssim_band_kernel<<<grid, NT, SMEM_BYTES>>>(sr, hr, out, bs);
}